// round 8
// baseline (speedup 1.0000x reference)
#include <cuda_runtime.h>
#include <cuda_bf16.h>
#include <cstdint>

#define BATCH 16
#define PD    31
#define COUT  16

#define A_PLANE 1088                         // 68 x-slots * 16B, plane = (yb,z)
#define A_YB    4352                         // 4 z-planes per yb
#define A_BYTES (8 * A_YB)                   // 34816
#define B_BYTES (9 * 2 * 16 * 16 * 2)        // 9216
#define AOFF    0
#define BOFF    A_BYTES                      // 34816
#define REDOFF  (BOFF + B_BYTES)             // 44032 : [8 warp][16 co]
#define SMEM_BYTES (REDOFF + 512)            // 44544

__device__ float g_part[BATCH * PD * COUT];

__device__ __forceinline__ uint32_t smem_u32(const void* p) {
    uint32_t a;
    asm("{ .reg .u64 t; cvta.to.shared.u64 t, %1; cvt.u32.u64 %0, t; }"
        : "=r"(a) : "l"(p));
    return a;
}

__device__ __forceinline__ uint32_t lds32(uint32_t addr) {
    uint32_t v;
    asm volatile("ld.shared.b32 %0, [%1];" : "=r"(v) : "r"(addr));
    return v;
}

__device__ __forceinline__ void ldsm4(uint32_t (&a)[4], uint32_t addr) {
    asm volatile("ldmatrix.sync.aligned.m8n8.x4.shared.b16 {%0,%1,%2,%3}, [%4];"
                 : "=r"(a[0]), "=r"(a[1]), "=r"(a[2]), "=r"(a[3]) : "r"(addr));
}

__device__ __forceinline__ void mma16816(float (&d)[4], const uint32_t (&a)[4],
                                         uint32_t b0, uint32_t b1) {
    asm volatile(
        "mma.sync.aligned.m16n8k16.row.col.f32.bf16.bf16.f32 "
        "{%0,%1,%2,%3}, {%4,%5,%6,%7}, {%8,%9}, {%0,%1,%2,%3};"
        : "+f"(d[0]), "+f"(d[1]), "+f"(d[2]), "+f"(d[3])
        : "r"(a[0]), "r"(a[1]), "r"(a[2]), "r"(a[3]), "r"(b0), "r"(b1));
}

__device__ __forceinline__ uint32_t bfpack(float fhi, float flo) {
    uint32_t r;
    asm("cvt.rn.bf16x2.f32 %0, %1, %2;" : "=r"(r) : "f"(fhi), "f"(flo));
    return r;
}

__global__ __launch_bounds__(256, 1)
void conv_mma_kernel(const float* __restrict__ x, const float* __restrict__ cw,
                     int pz0, int npz) {
    __shared__ __align__(1024) char smem[SMEM_BYTES];
    const uint32_t sbase = smem_u32(smem);
    const int tid  = threadIdx.x;
    const int wid  = tid >> 5;
    const int lane = tid & 31;
    const int b    = blockIdx.x / npz;
    const int pz   = pz0 + (blockIdx.x - b * npz);
    const float* xb = x + (size_t)b * 2097152;

    // ---- B tiles: [win9][kstep2][n16][k16] bf16 ----
    for (int i = tid; i < 4608; i += 256) {
        int k = i & 15, n = (i >> 4) & 15;
        int ks = (i >> 8) & 1, win = i >> 9;
        int dz = win / 3, dy = win % 3;
        int dxl = k >> 3, cin = k & 7, dx = ks * 2 + dxl;
        float w = (dx < 3) ? cw[(((n * 8 + cin) * 3 + dz) * 3 + dy) * 3 + dx] : 0.0f;
        *(__nv_bfloat16*)(smem + BOFF + i * 2) = __float2bfloat16(w);
    }
    // ---- zero x-pad slots (64..67) in all 32 planes ----
    for (int i = tid; i < 32 * 4 * 8; i += 256) {
        int p = i >> 5, xs = (i >> 3) & 3, c = i & 7;
        *(__nv_bfloat16*)(smem + AOFF + p * A_PLANE + (64 + xs) * 16 + c * 2) =
            __float2bfloat16(0.0f);
    }

    const int cp = tid & 3;
    const int xg = tid >> 2;
    auto ldrows = [&](int y0, uint32_t (&pk)[8]) {
#pragma unroll
        for (int j = 0; j < 8; ++j) {
            int zi = j >> 1, yy = j & 1;
            size_t base = ((size_t)((2 * cp) * 64 + (2 * pz + zi)) * 64 + (y0 + yy)) * 64 + xg;
            pk[j] = bfpack(xb[base + 262144], xb[base]);
        }
    };
    auto strows = [&](int y0, const uint32_t (&pk)[8]) {
#pragma unroll
        for (int j = 0; j < 8; ++j) {
            int zi = j >> 1, yy = j & 1;
            int yb = (y0 + yy) & 7;
            *(uint32_t*)(smem + AOFF + yb * A_YB + zi * A_PLANE + xg * 16 + cp * 4) = pk[j];
        }
    };

    {   // initial rows 0..3
        uint32_t pk[8];
        ldrows(0, pk); strows(0, pk);
        ldrows(2, pk); strows(2, pk);
    }
    __syncthreads();

    // m-row mapping: within-warp row rr = lane&15 -> x = wid*8 + rr>>1, oy = rr&1
    const int par    = lane & 1;
    const uint32_t SLOT16 = (uint32_t)((wid * 8 + ((lane & 15) >> 1) + (lane >> 4)) * 16);
    const uint32_t laneAz = sbase + AOFF + SLOT16;
    const uint32_t laneB  = sbase + BOFF + (lane >> 2) * 32 + (lane & 3) * 4;

    // ---- hoist all B fragments into registers ----
    uint32_t Breg[9][2][2][2];
#pragma unroll
    for (int win = 0; win < 9; ++win)
#pragma unroll
        for (int ks = 0; ks < 2; ++ks)
#pragma unroll
            for (int nt = 0; nt < 2; ++nt) {
                uint32_t a_ = laneB + win * 1024 + ks * 512 + nt * 256;
                Breg[win][ks][nt][0] = lds32(a_);
                Breg[win][ks][nt][1] = lds32(a_ + 16);
            }

    // px = wid*4 + (rr>>2); px 31 (x=62,63) is invalid -> mask
    const float mk23 = (wid == 7 && lane >= 16) ? 0.0f : 1.0f;

    float racc[2][4];
#pragma unroll
    for (int nt = 0; nt < 2; ++nt)
#pragma unroll
        for (int j = 0; j < 4; ++j) racc[nt][j] = 0.0f;

    float acc[2][2][4];
    uint32_t a[4][2][4];

    for (int t = 0; t < PD; ++t) {
        uint32_t pk[8];
        const bool pre = (t < PD - 1);
        if (pre) ldrows(2 * t + 4, pk);

#pragma unroll
        for (int oz = 0; oz < 2; ++oz)
#pragma unroll
            for (int nt = 0; nt < 2; ++nt)
#pragma unroll
                for (int j = 0; j < 4; ++j) acc[oz][nt][j] = 0.0f;

#pragma unroll
        for (int dy = 0; dy < 3; ++dy) {
            const uint32_t abase = laneAz + ((2 * t + dy + par) & 7) * A_YB;
#pragma unroll
            for (int zb = 0; zb < 4; ++zb) {
                const uint32_t pb = abase + zb * A_PLANE;
                ldsm4(a[zb][0], pb);
                ldsm4(a[zb][1], pb + 32);
            }
#pragma unroll
            for (int dz = 0; dz < 3; ++dz)
#pragma unroll
                for (int ks = 0; ks < 2; ++ks)
#pragma unroll
                    for (int nt = 0; nt < 2; ++nt)
#pragma unroll
                        for (int oz = 0; oz < 2; ++oz)
                            mma16816(acc[oz][nt], a[oz + dz][ks],
                                     Breg[dz * 3 + dy][ks][nt][0],
                                     Breg[dz * 3 + dy][ks][nt][1]);
        }

        // ---- register-only pooling: oz max, y-pair (xor4), x-pair (xor8) ----
#pragma unroll
        for (int nt = 0; nt < 2; ++nt) {
#pragma unroll
            for (int j = 0; j < 4; ++j) {
                float v = fmaxf(acc[0][nt][j], acc[1][nt][j]);
                v = fmaxf(v, __shfl_xor_sync(0xffffffffu, v, 4));
                v = fmaxf(v, __shfl_xor_sync(0xffffffffu, v, 8));
                if (j < 2) racc[nt][j] += v;
                else       racc[nt][j] = fmaf(mk23, v, racc[nt][j]);
            }
        }

        if (pre) strows(2 * t + 4, pk);
        __syncthreads();       // single barrier: protect A-ring slot reuse
    }

    // ---- final: combine px groups, reduce same-col lanes (dups -> x0.25) ----
    float s[4];
    s[0] = racc[0][0] + racc[0][2];
    s[1] = racc[0][1] + racc[0][3];
    s[2] = racc[1][0] + racc[1][2];
    s[3] = racc[1][1] + racc[1][3];
#pragma unroll
    for (int o = 4; o <= 16; o <<= 1)
#pragma unroll
        for (int q = 0; q < 4; ++q)
            s[q] += __shfl_xor_sync(0xffffffffu, s[q], o);

    float* red = (float*)(smem + REDOFF);
    if (lane < 4) {
        red[wid * 16 + lane * 2 + 0] = s[0] * 0.25f;
        red[wid * 16 + lane * 2 + 1] = s[1] * 0.25f;
        red[wid * 16 + 8 + lane * 2 + 0] = s[2] * 0.25f;
        red[wid * 16 + 8 + lane * 2 + 1] = s[3] * 0.25f;
    }
    __syncthreads();
    if (tid < COUT) {
        float S = 0.0f;
#pragma unroll
        for (int w = 0; w < 8; ++w) S += red[w * 16 + tid];
        g_part[(b * PD + pz) * COUT + tid] = S;
    }
}

__global__ void final_kernel(const float* __restrict__ cb,
                             const float* __restrict__ bias,
                             float* __restrict__ out) {
    __shared__ float sacc[256];
    const int t = threadIdx.x;
    const int b = t >> 4, co = t & 15;
    float S = 0.0f;
    for (int pz = 0; pz < PD; ++pz)
        S += g_part[(b * PD + pz) * COUT + co];
    sacc[t] = S * (0.5f / 29791.0f) + 0.5f * cb[co] + bias[co];
    __syncthreads();
    if (co == 0) {
        float s = 0.0f;
#pragma unroll
        for (int k = 0; k < COUT; ++k) s += sacc[b * COUT + k];
        out[b] = s;
    }
}

extern "C" void kernel_launch(void* const* d_in, const int* in_sizes, int n_in,
                              void* d_out, int out_size) {
    (void)in_sizes; (void)n_in; (void)out_size;
    const float* x    = (const float*)d_in[0];
    const float* cw   = (const float*)d_in[1];
    const float* cb   = (const float*)d_in[2];
    const float* bias = (const float*)d_in[3];
    float* out = (float*)d_out;

    conv_mma_kernel<<<BATCH * 16, 256>>>(x, cw, 0, 16);
    conv_mma_kernel<<<BATCH * 15, 256>>>(x, cw, 16, 15);
    final_kernel<<<1, 256>>>(cb, bias, out);
}

// round 9
// speedup vs baseline: 1.4603x; 1.4603x over previous
#include <cuda_runtime.h>
#include <cuda_bf16.h>
#include <cstdint>

#define BATCH 16
#define PD    31
#define COUT  16

// A smem: 16 planes ([zb4][yb4]) x 36 x-slots x 16B  (slots 34,35 = zero pad)
#define A_PLANE 576
#define A_BYTES (16 * A_PLANE)               // 9216
#define BOFF    A_BYTES                      // 9216
#define B_BYTES (9 * 2 * 16 * 16 * 2)        // 9216
#define POOLOFF (BOFF + B_BYTES)             // 18432 : [2 oy][16 px][16 co] f32
#define RED2OFF (POOLOFF + 2048)             // 20480 : [16 co][8 rpx] f32
#define SMEM_BYTES (RED2OFF + 512)           // 20992

__device__ float g_part[2 * BATCH * PD * COUT];

__device__ __forceinline__ uint32_t smem_u32(const void* p) {
    uint32_t a;
    asm("{ .reg .u64 t; cvta.to.shared.u64 t, %1; cvt.u32.u64 %0, t; }"
        : "=r"(a) : "l"(p));
    return a;
}

__device__ __forceinline__ uint32_t lds32(uint32_t addr) {
    uint32_t v;
    asm volatile("ld.shared.b32 %0, [%1];" : "=r"(v) : "r"(addr));
    return v;
}

__device__ __forceinline__ void ldsm4(uint32_t (&a)[4], uint32_t addr) {
    asm volatile("ldmatrix.sync.aligned.m8n8.x4.shared.b16 {%0,%1,%2,%3}, [%4];"
                 : "=r"(a[0]), "=r"(a[1]), "=r"(a[2]), "=r"(a[3]) : "r"(addr));
}

__device__ __forceinline__ void mma16816(float (&d)[4], const uint32_t (&a)[4],
                                         uint32_t b0, uint32_t b1) {
    asm volatile(
        "mma.sync.aligned.m16n8k16.row.col.f32.bf16.bf16.f32 "
        "{%0,%1,%2,%3}, {%4,%5,%6,%7}, {%8,%9}, {%0,%1,%2,%3};"
        : "+f"(d[0]), "+f"(d[1]), "+f"(d[2]), "+f"(d[3])
        : "r"(a[0]), "r"(a[1]), "r"(a[2]), "r"(a[3]), "r"(b0), "r"(b1));
}

__device__ __forceinline__ uint32_t bfpack(float fhi, float flo) {
    uint32_t r;
    asm("cvt.rn.bf16x2.f32 %0, %1, %2;" : "=r"(r) : "f"(fhi), "f"(flo));
    return r;
}

__global__ __launch_bounds__(128, 3)
void conv_mma_kernel(const float* __restrict__ x, const float* __restrict__ cw) {
    __shared__ __align__(1024) char smem[SMEM_BYTES];
    const uint32_t sbase = smem_u32(smem);
    const int tid  = threadIdx.x;
    const int wid  = tid >> 5;
    const int lane = tid & 31;
    const int half = blockIdx.x & 1;         // x-half: 0 -> x 0..31, 1 -> x 32..63
    const int bp   = blockIdx.x >> 1;
    const int b    = bp / PD;
    const int pz   = bp - b * PD;
    const float* xb = x + (size_t)b * 2097152;

    // ---- B tiles: [win9][kstep2][n16][k16] bf16 ----
    for (int i = tid; i < 4608; i += 128) {
        int k = i & 15, n = (i >> 4) & 15;
        int ks = (i >> 8) & 1, win = i >> 9;
        int dz = win / 3, dy = win % 3;
        int dxl = k >> 3, cin = k & 7, dx = ks * 2 + dxl;
        float w = (dx < 3) ? cw[(((n * 8 + cin) * 3 + dz) * 3 + dy) * 3 + dx] : 0.0f;
        *(__nv_bfloat16*)(smem + BOFF + i * 2) = __float2bfloat16(w);
    }
    // ---- zero pad slots 34,35 in all 16 planes ----
    for (int i = tid; i < 16 * 2 * 4; i += 128) {
        int p = i >> 3, sl = 34 + ((i >> 2) & 1), c = i & 3;
        *(uint32_t*)(smem + p * A_PLANE + sl * 16 + c * 4) = 0u;
    }

    // ---- converters: 2 y-rows x 4 z, slots 0..33 (half-local) ----
    const int cp = tid & 3;                  // cin pair
    const int sl = tid >> 2;                 // main slot 0..31 (always valid gx)
    const bool extra = (tid < 8);            // extra tasks: slots 32,33
    const int sl2 = 32 + (tid >> 2);
    const int gx  = half * 32 + sl;
    const int gx2 = half * 32 + sl2;
    const bool v2 = (gx2 < 64);

    auto ldrows = [&](int y0, uint32_t (&pk)[8], uint32_t (&pk2)[8]) {
#pragma unroll
        for (int j = 0; j < 8; ++j) {
            int zi = j >> 1, yy = j & 1;
            size_t base = ((size_t)((2 * cp) * 64 + (2 * pz + zi)) * 64 + (y0 + yy)) * 64;
            pk[j] = bfpack(xb[base + gx + 262144], xb[base + gx]);
            if (extra)
                pk2[j] = v2 ? bfpack(xb[base + gx2 + 262144], xb[base + gx2]) : 0u;
        }
    };
    auto strows = [&](int y0, const uint32_t (&pk)[8], const uint32_t (&pk2)[8]) {
#pragma unroll
        for (int j = 0; j < 8; ++j) {
            int zi = j >> 1, yy = j & 1;
            int yb = (y0 + yy) & 3;
            uint32_t po = (uint32_t)((zi * 4 + yb) * A_PLANE + cp * 4);
            *(uint32_t*)(smem + po + sl * 16) = pk[j];
            if (extra) *(uint32_t*)(smem + po + sl2 * 16) = pk2[j];
        }
    };

    {   // initial rows 0..3 -> ring slots 0..3
        uint32_t pk[8], pk2[8];
        ldrows(0, pk, pk2); strows(0, pk, pk2);
        ldrows(2, pk, pk2); strows(2, pk, pk2);
    }
    __syncthreads();

    const int oy   = wid >> 1;
    const int x0   = (wid & 1) * 16;
    const int r8   = lane & 7;
    const int matm = (lane >> 3) & 1;
    const int kh   = lane >> 4;
    const uint32_t laneA = sbase + (x0 + matm * 8 + r8) * 16 + kh * 16;
    const uint32_t laneB = sbase + BOFF + (lane >> 2) * 32 + (lane & 3) * 4;
    float* pool = (float*)(smem + POOLOFF);

    // ---- hoist all B fragments into registers (constant over t) ----
    uint32_t Breg[9][2][2][2];
#pragma unroll
    for (int win = 0; win < 9; ++win)
#pragma unroll
        for (int ks = 0; ks < 2; ++ks)
#pragma unroll
            for (int nt = 0; nt < 2; ++nt) {
                uint32_t a_ = laneB + win * 1024 + ks * 512 + nt * 256;
                Breg[win][ks][nt][0] = lds32(a_);
                Breg[win][ks][nt][1] = lds32(a_ + 16);
            }

    float racc0 = 0.0f, racc1 = 0.0f;
    const int rpx = tid >> 4, rco = tid & 15;        // 8 px x 16 co
    const bool px2ok = !(half == 1 && rpx == 7);     // global px 31 excluded

    for (int t = 0; t < PD; ++t) {
        uint32_t pk[8], pk2[8];
        const bool pre = (t < PD - 1);
        if (pre) ldrows(2 * t + 4, pk, pk2);

        float acc[2][2][4];
#pragma unroll
        for (int oz = 0; oz < 2; ++oz)
#pragma unroll
            for (int nt = 0; nt < 2; ++nt)
#pragma unroll
                for (int j = 0; j < 4; ++j) acc[oz][nt][j] = 0.0f;

#pragma unroll
        for (int dy = 0; dy < 3; ++dy) {
            const int yb = (2 * t + oy + dy) & 3;
            uint32_t a[4][2][4];
#pragma unroll
            for (int zb = 0; zb < 4; ++zb) {
                const uint32_t pb = laneA + (zb * 4 + yb) * A_PLANE;
                ldsm4(a[zb][0], pb);
                ldsm4(a[zb][1], pb + 32);
            }
#pragma unroll
            for (int dz = 0; dz < 3; ++dz)
#pragma unroll
                for (int ks = 0; ks < 2; ++ks)
#pragma unroll
                    for (int nt = 0; nt < 2; ++nt)
#pragma unroll
                        for (int oz = 0; oz < 2; ++oz)
                            mma16816(acc[oz][nt], a[oz + dz][ks],
                                     Breg[dz * 3 + dy][ks][nt][0],
                                     Breg[dz * 3 + dy][ks][nt][1]);
        }

        // ---- epilogue: max over oz, x-pair max via shfl-xor-4 ----
        float m[2][4];
#pragma unroll
        for (int nt = 0; nt < 2; ++nt)
#pragma unroll
            for (int j = 0; j < 4; ++j) {
                float v = fmaxf(acc[0][nt][j], acc[1][nt][j]);
                m[nt][j] = fmaxf(v, __shfl_xor_sync(0xffffffffu, v, 4));
            }
        if (((lane >> 2) & 1) == 0) {
            const int pxl = (lane >> 2) >> 1;
            const int px_ = (wid & 1) * 8 + pxl;
            const int c0  = 2 * (lane & 3);
            float* p0 = pool + (oy * 16 + px_) * 16;
            float* p1 = pool + (oy * 16 + px_ + 4) * 16;
            p0[c0]     = m[0][0];  p0[c0 + 1]     = m[0][1];
            p1[c0]     = m[0][2];  p1[c0 + 1]     = m[0][3];
            p0[8 + c0] = m[1][0];  p0[8 + c0 + 1] = m[1][1];
            p1[8 + c0] = m[1][2];  p1[8 + c0 + 1] = m[1][3];
        }
        __syncthreads();

        racc0 += fmaxf(pool[rpx * 16 + rco], pool[(16 + rpx) * 16 + rco]);
        if (px2ok) {
            const int px2 = rpx + 8;
            racc1 += fmaxf(pool[px2 * 16 + rco], pool[(16 + px2) * 16 + rco]);
        }
        if (pre) strows(2 * t + 4, pk, pk2);
        __syncthreads();
    }

    float* red2 = (float*)(smem + RED2OFF);
    red2[rco * 8 + rpx] = racc0 + racc1;
    __syncthreads();
    if (tid < COUT) {
        float s = 0.0f;
#pragma unroll
        for (int k = 0; k < 8; ++k) s += red2[tid * 8 + k];
        g_part[((half * BATCH + b) * PD + pz) * COUT + tid] = s;
    }
}

__global__ void final_kernel(const float* __restrict__ cb,
                             const float* __restrict__ bias,
                             float* __restrict__ out) {
    __shared__ float sacc[256];
    const int t = threadIdx.x;
    const int b = t >> 4, co = t & 15;
    float S = 0.0f;
#pragma unroll
    for (int h = 0; h < 2; ++h)
        for (int pz = 0; pz < PD; ++pz)
            S += g_part[((h * BATCH + b) * PD + pz) * COUT + co];
    sacc[t] = S * (0.5f / 29791.0f) + 0.5f * cb[co] + bias[co];
    __syncthreads();
    if (co == 0) {
        float s = 0.0f;
#pragma unroll
        for (int k = 0; k < COUT; ++k) s += sacc[b * COUT + k];
        out[b] = s;
    }
}

extern "C" void kernel_launch(void* const* d_in, const int* in_sizes, int n_in,
                              void* d_out, int out_size) {
    (void)in_sizes; (void)n_in; (void)out_size;
    const float* x    = (const float*)d_in[0];
    const float* cw   = (const float*)d_in[1];
    const float* cb   = (const float*)d_in[2];
    const float* bias = (const float*)d_in[3];
    float* out = (float*)d_out;

    conv_mma_kernel<<<2 * BATCH * PD, 128>>>(x, cw);
    final_kernel<<<1, 256>>>(cb, bias, out);
}

// round 10
// speedup vs baseline: 1.7427x; 1.1934x over previous
#include <cuda_runtime.h>
#include <cuda_bf16.h>
#include <cstdint>

#define BATCH 16
#define PD    31
#define COUT  16

#define A_PLANE 1088                         // 68 x-slots * 16B
#define A_BYTES (16 * A_PLANE)               // 17408 : [zb4][yb4] planes
#define B_BYTES (9 * 2 * 16 * 16 * 2)        // 9216
#define AOFF    0
#define BOFF    A_BYTES
#define POOLOFF (BOFF + B_BYTES)             // 26624 : [2 oy][32 px][16 co] f32
#define RED2OFF (POOLOFF + 4096)             // 30720 : [16 co][16] f32
#define SMEM_BYTES (RED2OFF + 1024)          // 31744

__device__ float g_part[BATCH * PD * COUT];

__device__ __forceinline__ uint32_t smem_u32(const void* p) {
    uint32_t a;
    asm("{ .reg .u64 t; cvta.to.shared.u64 t, %1; cvt.u32.u64 %0, t; }"
        : "=r"(a) : "l"(p));
    return a;
}

__device__ __forceinline__ uint32_t lds32(uint32_t addr) {
    uint32_t v;
    asm volatile("ld.shared.b32 %0, [%1];" : "=r"(v) : "r"(addr));
    return v;
}

__device__ __forceinline__ void ldsm4(uint32_t (&a)[4], uint32_t addr) {
    asm volatile("ldmatrix.sync.aligned.m8n8.x4.shared.b16 {%0,%1,%2,%3}, [%4];"
                 : "=r"(a[0]), "=r"(a[1]), "=r"(a[2]), "=r"(a[3]) : "r"(addr));
}

__device__ __forceinline__ void ldsm2(uint32_t& a0, uint32_t& a1, uint32_t addr) {
    asm volatile("ldmatrix.sync.aligned.m8n8.x2.shared.b16 {%0,%1}, [%2];"
                 : "=r"(a0), "=r"(a1) : "r"(addr));
}

__device__ __forceinline__ void mma16816(float (&d)[4], const uint32_t (&a)[4],
                                         uint32_t b0, uint32_t b1) {
    asm volatile(
        "mma.sync.aligned.m16n8k16.row.col.f32.bf16.bf16.f32 "
        "{%0,%1,%2,%3}, {%4,%5,%6,%7}, {%8,%9}, {%0,%1,%2,%3};"
        : "+f"(d[0]), "+f"(d[1]), "+f"(d[2]), "+f"(d[3])
        : "r"(a[0]), "r"(a[1]), "r"(a[2]), "r"(a[3]), "r"(b0), "r"(b1));
}

__device__ __forceinline__ void mma16808(float (&d)[4], uint32_t a0, uint32_t a1,
                                         uint32_t b0) {
    asm volatile(
        "mma.sync.aligned.m16n8k8.row.col.f32.bf16.bf16.f32 "
        "{%0,%1,%2,%3}, {%4,%5}, {%6}, {%0,%1,%2,%3};"
        : "+f"(d[0]), "+f"(d[1]), "+f"(d[2]), "+f"(d[3])
        : "r"(a0), "r"(a1), "r"(b0));
}

__device__ __forceinline__ uint32_t bfpack(float fhi, float flo) {
    uint32_t r;
    asm("cvt.rn.bf16x2.f32 %0, %1, %2;" : "=r"(r) : "f"(fhi), "f"(flo));
    return r;
}

__global__ __launch_bounds__(256, 2)
void conv_mma_kernel(const float* __restrict__ x, const float* __restrict__ cw,
                     int pz0, int npz) {
    __shared__ __align__(1024) char smem[SMEM_BYTES];
    const uint32_t sbase = smem_u32(smem);
    const int tid  = threadIdx.x;
    const int wid  = tid >> 5;
    const int lane = tid & 31;
    const int b    = blockIdx.x / npz;
    const int pz   = pz0 + (blockIdx.x - b * npz);
    const float* xb = x + (size_t)b * 2097152;

    // ---- B tiles: [win9][kstep2][n16][k16] bf16 ----
    for (int i = tid; i < 4608; i += 256) {
        int k = i & 15, n = (i >> 4) & 15;
        int ks = (i >> 8) & 1, win = i >> 9;
        int dz = win / 3, dy = win % 3;
        int dxl = k >> 3, cin = k & 7, dx = ks * 2 + dxl;
        float w = (dx < 3) ? cw[(((n * 8 + cin) * 3 + dz) * 3 + dy) * 3 + dx] : 0.0f;
        *(__nv_bfloat16*)(smem + BOFF + i * 2) = __float2bfloat16(w);
    }
    // ---- zero x-pad slots (64..67) in all 16 planes ----
    for (int i = tid; i < 16 * 4 * 8; i += 256) {
        int p = i >> 5, xs = (i >> 3) & 3, c = i & 7;
        *(__nv_bfloat16*)(smem + AOFF + p * A_PLANE + (64 + xs) * 16 + c * 2) =
            __float2bfloat16(0.0f);
    }

    const int cp = tid & 3;
    const int xg = tid >> 2;
    auto ldrows = [&](int y0, uint32_t (&pk)[8]) {
#pragma unroll
        for (int j = 0; j < 8; ++j) {
            int zi = j >> 1, yy = j & 1;
            size_t base = ((size_t)((2 * cp) * 64 + (2 * pz + zi)) * 64 + (y0 + yy)) * 64 + xg;
            pk[j] = bfpack(xb[base + 262144], xb[base]);
        }
    };
    auto strows = [&](int y0, const uint32_t (&pk)[8]) {
#pragma unroll
        for (int j = 0; j < 8; ++j) {
            int zi = j >> 1, yy = j & 1;
            int yb = (y0 + yy) & 3;
            *(uint32_t*)(smem + AOFF + (zi * 4 + yb) * A_PLANE + xg * 16 + cp * 4) = pk[j];
        }
    };

    {   // initial rows 0..3
        uint32_t pk[8];
        ldrows(0, pk); strows(0, pk);
        ldrows(2, pk); strows(2, pk);
    }
    __syncthreads();

    const int oy   = wid >> 2;
    const int x0   = (wid & 3) * 16;
    const int r8   = lane & 7;
    const int matm = (lane >> 3) & 1;
    const int kh   = lane >> 4;
    const uint32_t laneA = sbase + AOFF + (x0 + matm * 8 + r8) * 16 + kh * 16;
    const uint32_t laneB = sbase + BOFF + (lane >> 2) * 32 + (lane & 3) * 4;
    float* pool = (float*)(smem + POOLOFF);

    // ---- hoist B: k16 (dx0,1) 2 regs + k8 (dx2) 1 reg, per win x nt ----
    uint32_t B16[9][2][2], B8[9][2];
#pragma unroll
    for (int win = 0; win < 9; ++win)
#pragma unroll
        for (int nt = 0; nt < 2; ++nt) {
            uint32_t a0 = laneB + win * 1024 + nt * 256;          // ks0 tile
            B16[win][nt][0] = lds32(a0);
            B16[win][nt][1] = lds32(a0 + 16);
            B8[win][nt]     = lds32(a0 + 512);                    // ks1 tile, k<8 = dx2
        }

    float racc0 = 0.0f, racc1 = 0.0f;
    const int rpx = tid >> 4, rco = tid & 15;

    for (int t = 0; t < PD; ++t) {
        uint32_t pk[8];
        const bool pre = (t < PD - 1);
        if (pre) ldrows(2 * t + 4, pk);

        float acc[2][2][4];
#pragma unroll
        for (int oz = 0; oz < 2; ++oz)
#pragma unroll
            for (int nt = 0; nt < 2; ++nt)
#pragma unroll
                for (int j = 0; j < 4; ++j) acc[oz][nt][j] = 0.0f;

#pragma unroll
        for (int dy = 0; dy < 3; ++dy) {
            const int yb = (2 * t + oy + dy) & 3;
            uint32_t a16[4][4];
            uint32_t a8[4][2];
#pragma unroll
            for (int zb = 0; zb < 4; ++zb) {
                const uint32_t pb = laneA + (zb * 4 + yb) * A_PLANE;
                ldsm4(a16[zb], pb);                 // k16: dx0,1
                ldsm2(a8[zb][0], a8[zb][1], pb + 32);   // k8: dx2
            }
#pragma unroll
            for (int dz = 0; dz < 3; ++dz) {
                const int win = dz * 3 + dy;
#pragma unroll
                for (int nt = 0; nt < 2; ++nt)
#pragma unroll
                    for (int oz = 0; oz < 2; ++oz)
                        mma16816(acc[oz][nt], a16[oz + dz],
                                 B16[win][nt][0], B16[win][nt][1]);
#pragma unroll
                for (int nt = 0; nt < 2; ++nt)
#pragma unroll
                    for (int oz = 0; oz < 2; ++oz)
                        mma16808(acc[oz][nt], a8[oz + dz][0], a8[oz + dz][1],
                                 B8[win][nt]);
            }
        }

        // ---- epilogue: max over oz, x-pair max via shfl ----
        float m[2][4];
#pragma unroll
        for (int nt = 0; nt < 2; ++nt)
#pragma unroll
            for (int j = 0; j < 4; ++j) {
                float v = fmaxf(acc[0][nt][j], acc[1][nt][j]);
                m[nt][j] = fmaxf(v, __shfl_xor_sync(0xffffffffu, v, 4));
            }
        if (((lane >> 2) & 1) == 0) {
            const int pxl = (lane >> 2) >> 1;
            const int px_ = (wid & 3) * 8 + pxl;
            const int c0  = 2 * (lane & 3);
            float* p0 = pool + (oy * 32 + px_) * 16;
            float* p1 = pool + (oy * 32 + px_ + 4) * 16;
            p0[c0]     = m[0][0];  p0[c0 + 1]     = m[0][1];
            p1[c0]     = m[0][2];  p1[c0 + 1]     = m[0][3];
            p0[8 + c0] = m[1][0];  p0[8 + c0 + 1] = m[1][1];
            p1[8 + c0] = m[1][2];  p1[8 + c0 + 1] = m[1][3];
        }
        __syncthreads();

        racc0 += fmaxf(pool[rpx * 16 + rco], pool[(32 + rpx) * 16 + rco]);
        const int px2 = rpx + 16;
        if (px2 < 31)
            racc1 += fmaxf(pool[px2 * 16 + rco], pool[(32 + px2) * 16 + rco]);
        if (pre) strows(2 * t + 4, pk);
        __syncthreads();
    }

    float* red2 = (float*)(smem + RED2OFF);
    red2[rco * 16 + rpx] = racc0 + racc1;
    __syncthreads();
    if (tid < COUT) {
        float s = 0.0f;
#pragma unroll
        for (int k = 0; k < 16; ++k) s += red2[tid * 16 + k];
        g_part[(b * PD + pz) * COUT + tid] = s;
    }
}

__global__ void final_kernel(const float* __restrict__ cb,
                             const float* __restrict__ bias,
                             float* __restrict__ out) {
    __shared__ float sacc[256];
    const int t = threadIdx.x;
    const int b = t >> 4, co = t & 15;
    float S = 0.0f;
    for (int pz = 0; pz < PD; ++pz)
        S += g_part[(b * PD + pz) * COUT + co];
    sacc[t] = S * (0.5f / 29791.0f) + 0.5f * cb[co] + bias[co];
    __syncthreads();
    if (co == 0) {
        float s = 0.0f;
#pragma unroll
        for (int k = 0; k < COUT; ++k) s += sacc[b * COUT + k];
        out[b] = s;
    }
}

extern "C" void kernel_launch(void* const* d_in, const int* in_sizes, int n_in,
                              void* d_out, int out_size) {
    (void)in_sizes; (void)n_in; (void)out_size;
    const float* x    = (const float*)d_in[0];
    const float* cw   = (const float*)d_in[1];
    const float* cb   = (const float*)d_in[2];
    const float* bias = (const float*)d_in[3];
    float* out = (float*)d_out;

    conv_mma_kernel<<<BATCH * 16, 256>>>(x, cw, 0, 16);
    conv_mma_kernel<<<BATCH * 15, 256>>>(x, cw, 16, 15);
    final_kernel<<<1, 256>>>(cb, bias, out);
}